// round 10
// baseline (speedup 1.0000x reference)
#include <cuda_runtime.h>
#include <cuda_fp16.h>
#include <math.h>
#include <stdint.h>

#define NN 2048
#define DD 128
#define FF 8
#define TM 64               // i-rows per CTA
#define TNJ 64              // j-cols per tile
#define NTILE (NN / TNJ)    // 32
#define THREADS 512
#define NCTAS ((NN / TM) * FF)   // 256
#define LP 68               // label smem pitch (floats)

__device__ __half g_qh[FF * NN * DD];
__device__ __half g_dh[FF * NN * DD];
__device__ double g_loss;
__device__ int    g_count;
__device__ int    g_done;

__device__ __forceinline__ uint32_t smem_u32(const void* p) {
    uint32_t a;
    asm("{ .reg .u64 t; cvta.to.shared.u64 t, %1; cvt.u32.u64 %0, t; }" : "=r"(a) : "l"(p));
    return a;
}
__device__ __forceinline__ void cpa16(uint32_t dst, const void* src) {
    asm volatile("cp.async.cg.shared.global [%0], [%1], 16;" :: "r"(dst), "l"(src) : "memory");
}
#define CP_COMMIT() asm volatile("cp.async.commit_group;" ::: "memory")
#define CP_WAIT0()  asm volatile("cp.async.wait_group 0;" ::: "memory")

#define LDSM4(r, addr) \
    asm volatile("ldmatrix.sync.aligned.m8n8.x4.shared.b16 {%0,%1,%2,%3}, [%4];" \
                 : "=r"((r)[0]), "=r"((r)[1]), "=r"((r)[2]), "=r"((r)[3]) : "r"(addr))

__device__ __forceinline__ void mma_f16(float* c, const uint32_t* a, const uint32_t* b) {
    asm volatile(
        "mma.sync.aligned.m16n8k16.row.col.f32.f16.f16.f32 "
        "{%0,%1,%2,%3}, {%4,%5,%6,%7}, {%8,%9}, {%0,%1,%2,%3};"
        : "+f"(c[0]), "+f"(c[1]), "+f"(c[2]), "+f"(c[3])
        : "r"(a[0]), "r"(a[1]), "r"(a[2]), "r"(a[3]), "r"(b[0]), "r"(b[1]));
}

__device__ __forceinline__ uint32_t swz(int row, int chunk) {
    return (uint32_t)(row * 256 + ((chunk ^ (row & 7)) << 4));
}

// SMEM layout: A 16K | B0 16K | B1 16K | L0 17K | L1 17K | diag
#define SM_AH   0
#define SM_B0   16384
#define SM_BSTR 16384
#define SM_L0   49152
#define SM_LSTR 17408       // 64 * 68 * 4
#define SM_DIAG 83968
#define SM_TOTAL (83968 + 512)

// ---------------- prep: normalize -> fp16 ----------------
__global__ void k_norm(const float* __restrict__ in0) {
    __shared__ float sd[DD * 9 + 9];
    int s = blockIdx.y, n = blockIdx.x;
    int tid = threadIdx.x;
    int f = tid >> 5, lane = tid & 31;
    const float4* base = (const float4*)(in0 + ((size_t)(s * NN + n)) * DD * FF);
    float4 v4 = base[tid];
    {
        int e = tid * 4;
        sd[((e + 0) >> 3) * 9 + ((e + 0) & 7)] = v4.x;
        sd[((e + 1) >> 3) * 9 + ((e + 1) & 7)] = v4.y;
        sd[((e + 2) >> 3) * 9 + ((e + 2) & 7)] = v4.z;
        sd[((e + 3) >> 3) * 9 + ((e + 3) & 7)] = v4.w;
    }
    __syncthreads();
    float v[4], ssq = 0.f;
#pragma unroll
    for (int k = 0; k < 4; k++) {
        v[k] = sd[(lane + 32 * k) * 9 + f];
        ssq += v[k] * v[k];
    }
#pragma unroll
    for (int off = 16; off; off >>= 1) ssq += __shfl_xor_sync(0xffffffffu, ssq, off);
    float rn = 1.0f / sqrtf(ssq);
    __half* oh = (s == 0 ? g_qh : g_dh) + ((size_t)(f * NN + n)) * DD;
#pragma unroll
    for (int k = 0; k < 4; k++)
        oh[lane + 32 * k] = __float2half_rn(v[k] * rn);
}

// fp16 tile: 64 rows x 128 cols, swizzled; 1024 chunks / 512 threads = 2 iters
__device__ __forceinline__ void load_tile_async(uint32_t smbase, const __half* src, int tid) {
#pragma unroll
    for (int it = 0; it < (64 * 16) / THREADS; it++) {
        int idx = tid + it * THREADS;
        int row = idx >> 4, c = idx & 15;
        cpa16(smbase + swz(row, c), src + row * DD + c * 8);
    }
}

// label tile: 64 rows x 64 floats -> pitch LP
__device__ __forceinline__ void load_lab_async(uint32_t smbase, const float* src, int tid) {
#pragma unroll
    for (int it = 0; it < 2; it++) {
        int idx = tid + it * THREADS;
        int row = idx >> 4, c = idx & 15;
        cpa16(smbase + (uint32_t)(row * (LP * 4) + c * 16), src + (size_t)row * NN + c * 4);
    }
}

// ---------------- main ----------------
__global__ void __launch_bounds__(THREADS, 2) k_gemm(const float* __restrict__ label,
                                                     const float* __restrict__ pmargin,
                                                     float* __restrict__ gout, int nout) {
    extern __shared__ __align__(1024) char sm[];
    const uint32_t smb = smem_u32(sm);
    const int tid = threadIdx.x;
    const int w = tid >> 5, lane = tid & 31;
    const int g = lane >> 2, t4 = lane & 3;
    const int rowgrp = w >> 2, colgrp = w & 3;     // 4 x 4 warp grid: 16 rows x 16 cols
    const int f = blockIdx.y;
    const int i0 = blockIdx.x * TM;
    const float margin = *pmargin;
    const size_t fb = (size_t)f * NN;
    float* sdS = (float*)(sm + SM_DIAG);
    float* sdL = sdS + TM;

    load_tile_async(smb + SM_AH, g_qh + (fb + i0) * DD, tid);
    load_tile_async(smb + SM_B0, g_dh + fb * DD, tid);
    load_lab_async(smb + SM_L0, label + (fb + i0) * NN, tid);
    CP_COMMIT();

    // fused diag: warp w -> rows w*4 .. w*4+3
    {
        const int d = lane * 4;
#pragma unroll 1
        for (int r4 = 0; r4 < 4; r4++) {
            int row = w * 4 + r4;
            const __half* qh = g_qh + (fb + i0 + row) * DD;
            const __half* dh = g_dh + (fb + i0 + row) * DD;
            float s = 0.f;
#pragma unroll
            for (int u = 0; u < 4; u++)
                s += __half2float(qh[d + u]) * __half2float(dh[d + u]);
#pragma unroll
            for (int off = 16; off; off >>= 1) s += __shfl_xor_sync(0xffffffffu, s, off);
            if (lane == 0) {
                sdS[row] = s;
                sdL[row] = label[(fb + i0 + row) * NN + (i0 + row)];
            }
        }
    }

    CP_WAIT0();
    __syncthreads();

    int rloc[2];
    rloc[0] = rowgrp * 16 + g;
    rloc[1] = rloc[0] + 8;
    float dS[2], dL[2];
    dS[0] = sdS[rloc[0]]; dL[0] = sdL[rloc[0]];
    dS[1] = sdS[rloc[1]]; dL[1] = sdL[rloc[1]];

    float smax[2] = {-INFINITY, -INFINITY}, lmax[2] = {-INFINITY, -INFINITY};
    int sidx[2] = {0, 0}, lidx[2] = {0, 0};
    float loss = 0.f;

    const int arow = rowgrp * 16 + (lane & 15);
    const int ahalf = lane >> 4;
    // B x4: matrices = {cols 0-7 kh0, cols 0-7 kh1, cols 8-15 kh0, cols 8-15 kh1}
    const int brow = colgrp * 16 + ((lane >> 4) & 1) * 8 + (lane & 7);
    const int bhalf = (lane >> 3) & 1;
    const int jl0 = colgrp * 16 + t4 * 2;

#pragma unroll 1
    for (int t = 0; t < NTILE; t++) {
        if (t + 1 < NTILE) {
            uint32_t buf = (uint32_t)((t + 1) & 1);
            load_tile_async(smb + SM_B0 + buf * SM_BSTR,
                            g_dh + (fb + (size_t)(t + 1) * TNJ) * DD, tid);
            load_lab_async(smb + SM_L0 + buf * SM_LSTR,
                           label + (fb + i0) * NN + (size_t)(t + 1) * TNJ, tid);
            CP_COMMIT();
        }
        const uint32_t bb = smb + SM_B0 + (uint32_t)(t & 1) * SM_BSTR;
        const float* ls = (const float*)(sm + SM_L0 + (t & 1) * SM_LSTR);
        const int j0 = t * TNJ;

        // label reg prefetch (LDS latency hides under the MMA loop)
        float2 lab[2][2];
#pragma unroll
        for (int nt = 0; nt < 2; nt++)
#pragma unroll
            for (int k = 0; k < 2; k++)
                lab[nt][k] = *(const float2*)&ls[rloc[k] * LP + jl0 + nt * 8];

        float acc[2][4];
#pragma unroll
        for (int nt = 0; nt < 2; nt++)
#pragma unroll
            for (int u = 0; u < 4; u++) acc[nt][u] = 0.f;

#pragma unroll
        for (int ks = 0; ks < 8; ks++) {
            uint32_t a[4], b[4];
            LDSM4(a, smb + SM_AH + swz(arow, 2 * ks + ahalf));
            LDSM4(b, bb + swz(brow, 2 * ks + bhalf));
            mma_f16(acc[0], a, b + 0);
            mma_f16(acc[1], a, b + 2);
        }

        // epilogue: 8 elems/thread (diag contributes exactly `margin`; fixed at finalize)
#pragma unroll
        for (int nt = 0; nt < 2; nt++) {
            const int j = j0 + jl0 + nt * 8;
#pragma unroll
            for (int k = 0; k < 2; k++) {
                float2 l2 = lab[nt][k];
                float s0 = acc[nt][2 * k + 0];
                float s1 = acc[nt][2 * k + 1];
                if (s0 > smax[k]) { smax[k] = s0; sidx[k] = j; }
                if (s1 > smax[k]) { smax[k] = s1; sidx[k] = j + 1; }
                if (l2.x > lmax[k]) { lmax[k] = l2.x; lidx[k] = j; }
                if (l2.y > lmax[k]) { lmax[k] = l2.y; lidx[k] = j + 1; }
                loss += fmaxf(margin - (dS[k] - s0) * (dL[k] - l2.x), 0.f);
                loss += fmaxf(margin - (dS[k] - s1) * (dL[k] - l2.y), 0.f);
            }
        }

        if (t + 1 < NTILE) {
            CP_WAIT0();
            __syncthreads();
        }
    }

    // ---- loss ----
#pragma unroll
    for (int off = 16; off; off >>= 1) loss += __shfl_xor_sync(0xffffffffu, loss, off);
    if (lane == 0) atomicAdd(&g_loss, (double)loss);

    // ---- argmax: quad reduce then cross-colgrp merge ----
#pragma unroll
    for (int k = 0; k < 2; k++) {
#pragma unroll
        for (int o = 1; o < 4; o <<= 1) {
            float v; int ix;
            v = __shfl_xor_sync(0xffffffffu, smax[k], o); ix = __shfl_xor_sync(0xffffffffu, sidx[k], o);
            if (v > smax[k] || (v == smax[k] && ix < sidx[k])) { smax[k] = v; sidx[k] = ix; }
            v = __shfl_xor_sync(0xffffffffu, lmax[k], o); ix = __shfl_xor_sync(0xffffffffu, lidx[k], o);
            if (v > lmax[k] || (v == lmax[k] && ix < lidx[k])) { lmax[k] = v; lidx[k] = ix; }
        }
    }

    __syncthreads();                    // A smem dead -> reuse
    float* ms = (float*)sm;             // [4][64]
    int*   mi = (int*)(sm + 1024);
    float* Ls = (float*)(sm + 2048);
    int*   Li = (int*)(sm + 3072);
    if (t4 == 0) {
#pragma unroll
        for (int k = 0; k < 2; k++) {
            ms[colgrp * TM + rloc[k]] = smax[k];
            mi[colgrp * TM + rloc[k]] = sidx[k];
            Ls[colgrp * TM + rloc[k]] = lmax[k];
            Li[colgrp * TM + rloc[k]] = lidx[k];
        }
    }
    __syncthreads();
    int match = 0;
    if (tid < TM) {
        float bs = -INFINITY, bl = -INFINITY;
        int bsi = 0, bli = 0;
#pragma unroll
        for (int c = 0; c < 4; c++) {
            float v = ms[c * TM + tid]; int ix = mi[c * TM + tid];
            if (v > bs || (v == bs && ix < bsi)) { bs = v; bsi = ix; }
            float u = Ls[c * TM + tid]; int jx = Li[c * TM + tid];
            if (u > bl || (u == bl && jx < bli)) { bl = u; bli = jx; }
        }
        match = (bsi == bli);
    }
    match = __reduce_add_sync(0xffffffffu, match);
    if (lane == 0 && w < (TM / 32) && match) atomicAdd(&g_count, match);

    // ---- fused finalize ----
    __syncthreads();
    if (tid == 0) {
        __threadfence();
        int old = atomicAdd(&g_done, 1);
        if (old == NCTAS - 1) {
            double L = atomicAdd(&g_loss, 0.0);
            int    C = atomicAdd(&g_count, 0);
            double corr = (double)(FF * NN) * (double)fmaxf(margin, 0.f);
            if (nout > 0) gout[0] = (float)(L - corr);
            if (nout > 1) gout[1] = (float)C;
            g_loss = 0.0;
            g_count = 0;
            __threadfence();
            g_done = 0;
        }
    }
}

extern "C" void kernel_launch(void* const* d_in, const int* in_sizes, int n_in,
                              void* d_out, int out_size) {
    const float* out_matrix = (const float*)d_in[0];
    const float* label      = (const float*)d_in[1];
    const float* margin     = (const float*)d_in[2];
    float* out = (float*)d_out;

    cudaFuncSetAttribute(k_gemm, cudaFuncAttributeMaxDynamicSharedMemorySize, SM_TOTAL);

    dim3 gn(NN, 2);
    k_norm<<<gn, 256>>>(out_matrix);
    dim3 gm(NN / TM, FF);
    k_gemm<<<gm, THREADS, SM_TOTAL>>>(label, margin, out, out_size);
}